// round 15
// baseline (speedup 1.0000x reference)
#include <cuda_runtime.h>
#include <cuda_fp16.h>
#include <math.h>

#define OUT_F 512
#define IN_F  1024
#define NPAIR 128          // batch pairs (2 rows per half2 lane)
#define NSPLIT 8           // i-splits of 128 inputs each
#define JTILE  16          // output nodes per block
#define NJT    (OUT_F / JTILE)   // 32 j-columns

// Scratch (device globals — no allocation allowed anywhere)
__device__ __half2  g_P[NSPLIT * OUT_F * NPAIR];  // partials [s][j][p]
__device__ unsigned g_cnt[NJT];                   // zero-init; reset by last block

static __device__ __forceinline__ __half2 u2h2(unsigned v) {
    return *reinterpret_cast<__half2*>(&v);
}

// Hard gumbel argmax decision -> 32-bit select mask.
// g(u) = -log(-log(u+eps)+eps) is strictly increasing, so for c0 == c1 the
// argmax is exactly (u1 > u0); ties -> index 0 = edge, matching jnp.argmax.
// General-c fallback keeps the bit-verified logf path.
static __device__ __forceinline__ unsigned edge_mask(float c0, float c1,
                                                     float u0, float u1)
{
    bool no_edge;
    if (c0 == c1) {
        no_edge = u1 > u0;
    } else {
        const float eps = 1e-10f;
        float g0 = -logf(-logf(u0 + eps) + eps);
        float g1 = -logf(-logf(u1 + eps) + eps);
        no_edge = (c1 + g1) > (c0 + g0);
    }
    return no_edge ? 0xFFFFFFFFu : 0u;
}

// ---------------------------------------------------------------------------
// Single fused kernel. Block (s, jt): 256 threads = 2 groups of 128.
// Group g handles sub-slices {2g, 2g+1} of the block's 128 inputs (32 i each):
//   stage x as fp16 (coalesced loads, odd-stride SMEM rows), build the 16x32
//   edge masks inline from etc/noise, then per half2 element:
//   1 LOP3 (alu pipe) + 1 HMNMX2 (fma pipe); select constant = EXACT
//   reference no-edge offset (2.0 / -1.0) -> no clamp, identity = offset.
// Groups merge through SMEM; block writes its partial; the LAST block of each
// j-column (atomic counter) combines the 8 partials and writes out directly.
// Grid 8x32 = 256 blocks x 8 warps = 2048 warps co-resident.
// ---------------------------------------------------------------------------
__global__ __launch_bounds__(256) void daa_fused_kernel(
    const float* __restrict__ etc, const float* __restrict__ noise,
    const float* __restrict__ x, float* __restrict__ out)
{
    // Manual SMEM layout (37,632 B): xh[2][32][258] halves | Ms[2][16][36] u32.
    // cb[2][16][128] half2 (16 KB) aliases the xh region after xh is dead.
    __shared__ __align__(16) unsigned char smraw[2 * 32 * 258 * 2 + 2 * JTILE * 36 * 4];
    __half   (*xh)[32][258]      = reinterpret_cast<__half(*)[32][258]>(smraw);
    unsigned (*Ms)[JTILE][36]    = reinterpret_cast<unsigned(*)[JTILE][36]>(smraw + 33024);
    __half2  (*cb)[JTILE][NPAIR] = reinterpret_cast<__half2(*)[JTILE][NPAIR]>(smraw);
    __shared__ int isLastS;

    const int s  = blockIdx.x;            // 0..7
    const int jt = blockIdx.y;            // 0..31
    const int j0 = jt * JTILE;
    const int t  = threadIdx.x;
    const int g  = t >> 7;                // i-group
    const int tp = t & 127;               // batch-pair index
    const int li = tp & 31;
    const int w  = tp >> 5;

    const unsigned OFFP = 0x40004000u;    // half2(+2.0): min-node no-edge value
    const unsigned OFFN = 0xBC00BC00u;    // half2(-1.0): max-node no-edge value
    const __half2 PI = u2h2(OFFP);
    const __half2 NI = u2h2(OFFN);

    // Persistent accumulators: 8 (min,max) node pairs x 2 ILP chains
    __half2 m0a[8], m1a[8], M0a[8], M1a[8];
    #pragma unroll
    for (int p = 0; p < 8; p++) { m0a[p] = PI; m1a[p] = PI; M0a[p] = NI; M1a[p] = NI; }

    #pragma unroll 1
    for (int sub = 0; sub < 2; sub++) {
        const int i0 = s * 128 + g * 64 + sub * 32;
        if (sub) __syncthreads();         // protect smem reuse

        // Stage x sub-slice as fp16: warp w loads rows w*64.., 128B coalesced
        #pragma unroll
        for (int k = 0; k < 64; k++) {
            int b = w * 64 + k;
            xh[g][li][b] = __float2half(x[b * IN_F + i0 + li]);
        }

        // Inline mask build: thread (jl = tp/8, c = tp%8) handles 4 elements
        {
            const int jl = tp >> 3, c = tp & 7;
            const size_t rb = ((size_t)(j0 + jl) * IN_F + i0) * 2;  // float offset
            const float4* ep = reinterpret_cast<const float4*>(etc   + rb) + 2 * c;
            const float4* np = reinterpret_cast<const float4*>(noise + rb) + 2 * c;
            float4 e0 = ep[0], e1 = ep[1];
            float4 n0 = np[0], n1 = np[1];
            uint4 mm;
            mm.x = edge_mask(e0.x, e0.y, n0.x, n0.y);
            mm.y = edge_mask(e0.z, e0.w, n0.z, n0.w);
            mm.z = edge_mask(e1.x, e1.y, n1.x, n1.y);
            mm.w = edge_mask(e1.z, e1.w, n1.z, n1.w);
            *reinterpret_cast<uint4*>(&Ms[g][jl][4 * c]) = mm;      // 16B aligned
        }
        __syncthreads();

        // This pair's 32 x half2: one aligned LDS.32 each (row stride 129 words)
        unsigned xr[32];
        #pragma unroll
        for (int k = 0; k < 32; k++)
            xr[k] = *reinterpret_cast<const unsigned*>(&xh[g][k][2 * tp]);

        // (min-node, max-node) pairs; j0 even -> jj even -> t-norm (min)
        #pragma unroll
        for (int jj = 0; jj < JTILE; jj += 2) {
            __half2 m0 = m0a[jj >> 1], m1 = m1a[jj >> 1];
            __half2 M0 = M0a[jj >> 1], M1 = M1a[jj >> 1];
            const uint4* a0p = reinterpret_cast<const uint4*>(&Ms[g][jj][0]);
            const uint4* a1p = reinterpret_cast<const uint4*>(&Ms[g][jj + 1][0]);
            #pragma unroll
            for (int q = 0; q < 8; q++) {
                uint4 a0 = a0p[q];                    // LDS.128 uniform -> broadcast
                uint4 a1 = a1p[q];
                m0 = __hmin2(m0, u2h2((a0.x & OFFP) | (~a0.x & xr[4 * q + 0])));
                m1 = __hmin2(m1, u2h2((a0.y & OFFP) | (~a0.y & xr[4 * q + 1])));
                m0 = __hmin2(m0, u2h2((a0.z & OFFP) | (~a0.z & xr[4 * q + 2])));
                m1 = __hmin2(m1, u2h2((a0.w & OFFP) | (~a0.w & xr[4 * q + 3])));
                M0 = __hmax2(M0, u2h2((a1.x & OFFN) | (~a1.x & xr[4 * q + 0])));
                M1 = __hmax2(M1, u2h2((a1.y & OFFN) | (~a1.y & xr[4 * q + 1])));
                M0 = __hmax2(M0, u2h2((a1.z & OFFN) | (~a1.z & xr[4 * q + 2])));
                M1 = __hmax2(M1, u2h2((a1.w & OFFN) | (~a1.w & xr[4 * q + 3])));
            }
            m0a[jj >> 1] = m0; m1a[jj >> 1] = m1;
            M0a[jj >> 1] = M0; M1a[jj >> 1] = M1;
        }
    }

    // Cross-group merge through SMEM (cb aliases dead xh region)
    __syncthreads();
    #pragma unroll
    for (int jj = 0; jj < JTILE; jj += 2) {
        cb[g][jj + 0][tp] = __hmin2(m0a[jj >> 1], m1a[jj >> 1]);
        cb[g][jj + 1][tp] = __hmax2(M0a[jj >> 1], M1a[jj >> 1]);
    }
    __syncthreads();
    if (g == 0) {
        #pragma unroll
        for (int jj = 0; jj < JTILE; jj += 2) {
            g_P[(s * OUT_F + j0 + jj + 0) * NPAIR + tp] = __hmin2(cb[0][jj + 0][tp], cb[1][jj + 0][tp]);
            g_P[(s * OUT_F + j0 + jj + 1) * NPAIR + tp] = __hmax2(cb[0][jj + 1][tp], cb[1][jj + 1][tp]);
        }
    }
    __syncthreads();

    // Last block of this j-column combines the 8 partials (threadfence pattern)
    if (t == 0) {
        __threadfence();
        unsigned old = atomicAdd(&g_cnt[jt], 1);
        isLastS = (old == NSPLIT - 1);
        if (isLastS) atomicExch(&g_cnt[jt], 0);   // reset for next graph replay
    }
    __syncthreads();
    if (isLastS) {
        const unsigned* pb = reinterpret_cast<const unsigned*>(g_P);
        #pragma unroll 1
        for (int k = 0; k < 8; k++) {
            int jj = 2 * k + g;                   // parity(jj) == g: warp-uniform
            int j  = j0 + jj;
            if (g == 0) {
                __half2 acc = PI;
                #pragma unroll
                for (int sp = 0; sp < NSPLIT; sp++)
                    acc = __hmin2(acc, u2h2(__ldcg(pb + ((size_t)sp * OUT_F + j) * NPAIR + tp)));
                out[(2 * tp + 0) * OUT_F + j] = __low2float(acc);
                out[(2 * tp + 1) * OUT_F + j] = __high2float(acc);
            } else {
                __half2 acc = NI;
                #pragma unroll
                for (int sp = 0; sp < NSPLIT; sp++)
                    acc = __hmax2(acc, u2h2(__ldcg(pb + ((size_t)sp * OUT_F + j) * NPAIR + tp)));
                out[(2 * tp + 0) * OUT_F + j] = __low2float(acc);
                out[(2 * tp + 1) * OUT_F + j] = __high2float(acc);
            }
        }
    }
}

// ---------------------------------------------------------------------------
extern "C" void kernel_launch(void* const* d_in, const int* in_sizes, int n_in,
                              void* d_out, int out_size)
{
    const float* x     = (const float*)d_in[0];   // [256, 1024]
    const float* etc   = (const float*)d_in[1];   // [512, 1024, 2]
    const float* noise = (const float*)d_in[2];   // [512, 1024, 2]
    float* out = (float*)d_out;                   // [256, 512]

    daa_fused_kernel<<<dim3(NSPLIT, NJT), 256>>>(etc, noise, x, out);
}